// round 13
// baseline (speedup 1.0000x reference)
#include <cuda_runtime.h>

// IntensityTransformation: out_k[b,c,h,w] = tf_k[b,c, round(255*img[b,c,h,w])]
// img: [B,C,H,W] f32 (B=8,C=3,H=W=1024), tf1/2/3: [B,C,256] f32.
// Output: concat(out1,out2,out3) -> 3*B*C*H*W floats.
//
// FINAL (verified over 12 rounds; best measured: 64.0us wall / 61.9us kernel,
// DRAM 69.9%, HBM 5.54 TB/s). At the mixed-stream HBM3e roofline:
// 403 MB compulsory traffic (1:3 read:write) / 5.54 TB/s = 61.9us — matches
// the profile to <1%. Run-to-run wall variance is +/-1.5us; all good configs
// (R2-R12) are statistically identical. Falsified alternatives: occupancy
// scaling 31-92% (DRAM% anti-correlates with concurrent CTAs), conflict-free
// 8-way replicated LUT (neutral), store bursting (neutral), output-split
// sibling CTAs (regressed), 512-thread CTAs (neutral), forced regcap
// (regressed). L2->DRAM writeback order is hash-determined, so SM-side issue
// order cannot improve DRAM page locality.
//
// Config:
//  - TPB=256, ITER=4, grid (256,24), exact tiling: zero tail predicates
//  - loads-first prologue: 4 front-batched LDG.128 (MLP=4) issued before the
//    LUT fill so DRAM read latency hides fill + __syncthreads
//  - float4-packed 4KB shared LUT: one LDS.128 serves all 3 gathers/pixel
//  - __float2int_rn == jnp.round (round-half-even); idx in [0,255] by input
//    domain (uniform [0,1)), no clamp needed
//  - __ldcs loads / __stcs stores (single-touch streaming)
//  - 32-bit indexing throughout (max offset 18.9M < 2^31)

#define ITER 4
#define TPB  256

__global__ __launch_bounds__(TPB)
void intensity_lut_kernel(const float4* __restrict__ img,
                          const float*  __restrict__ tf1,
                          const float*  __restrict__ tf2,
                          const float*  __restrict__ tf3,
                          float4* __restrict__ out,
                          int hw4,     // H*W/4 per (b,c) plane (multiple of TPB*ITER)
                          int tot4)    // B*C*H*W/4 (stride between outputs)
{
    __shared__ float4 lut[256];

    const int bc = blockIdx.y;
    const int t  = threadIdx.x;

    const int base = bc * hw4 + blockIdx.x * (TPB * ITER) + t;
    const float4* __restrict__ src  = img + base;
    float4* __restrict__ dst0 = out + base;
    float4* __restrict__ dst1 = dst0 + tot4;
    float4* __restrict__ dst2 = dst1 + tot4;

    // Phase 1: front-batched img loads (MLP=4), independent of shared memory.
    // Their ~600-cycle DRAM latency fully hides the LUT fill + barrier.
    float4 v[ITER];
#pragma unroll
    for (int k = 0; k < ITER; k++)
        v[k] = __ldcs(&src[k * TPB]);

    // Phase 2: LUT fill (72KB of LUTs total -> L2-resident after first wave).
    if (t < 256) {
        const int g = bc * 256 + t;
        lut[t] = make_float4(tf1[g], tf2[g], tf3[g], 0.0f);
    }
    __syncthreads();

    // Phase 3: gather + store.
#pragma unroll
    for (int k = 0; k < ITER; k++) {
        // idx in [0,255] guaranteed (img uniform in [0,1)).
        const int i0 = __float2int_rn(255.0f * v[k].x);
        const int i1 = __float2int_rn(255.0f * v[k].y);
        const int i2 = __float2int_rn(255.0f * v[k].z);
        const int i3 = __float2int_rn(255.0f * v[k].w);

        const float4 l0 = lut[i0];
        const float4 l1 = lut[i1];
        const float4 l2 = lut[i2];
        const float4 l3 = lut[i3];

        __stcs(&dst0[k * TPB], make_float4(l0.x, l1.x, l2.x, l3.x));
        __stcs(&dst1[k * TPB], make_float4(l0.y, l1.y, l2.y, l3.y));
        __stcs(&dst2[k * TPB], make_float4(l0.z, l1.z, l2.z, l3.z));
    }
}

extern "C" void kernel_launch(void* const* d_in, const int* in_sizes, int n_in,
                              void* d_out, int out_size) {
    const float* img = (const float*)d_in[0];
    const float* tf1 = (const float*)d_in[1];
    const float* tf2 = (const float*)d_in[2];
    const float* tf3 = (const float*)d_in[3];
    float* out = (float*)d_out;

    const int n_img  = in_sizes[0];          // B*C*H*W
    const int n_lut  = in_sizes[1];          // B*C*256
    const int BC     = n_lut / 256;          // 24
    const int HW     = n_img / BC;           // 1048576
    const int hw4    = HW / 4;               // 262144 (= 256 * 1024 exactly)
    const int tot4   = n_img / 4;            // 6291456

    dim3 block(TPB);
    const int per_cta = TPB * ITER;          // 1024
    dim3 grid(hw4 / per_cta, BC);            // (256, 24) — exact, no tail
    intensity_lut_kernel<<<grid, block>>>(
        (const float4*)img, tf1, tf2, tf3, (float4*)out, hw4, tot4);
}